// round 7
// baseline (speedup 1.0000x reference)
#include <cuda_runtime.h>
#include <cuda_fp16.h>

#define TT  30
#define TD  150
#define DIM 512
#define MAX_ROWS 34836   // WORDS_CNT + 1

// fp16 copy of the embedding table (zero-init .bss, no allocation)
__device__ __half g_w2v_h[(size_t)MAX_ROWS * DIM];

// ---- pass 1: fp32 -> fp16 table conversion ----------------------------------
// Each thread: 2 float4 loads -> 1 uint4 store per unit. Grid-stride, unroll 4.
__global__ __launch_bounds__(256)
void w2v_convert_kernel(const float4* __restrict__ src, uint4* __restrict__ dst, int nOut)
{
    const int stride = gridDim.x * 256;
    int i = blockIdx.x * 256 + threadIdx.x;

    for (; i + 3 * stride < nOut; i += 4 * stride) {
        float4 fa[4], fb[4];
        #pragma unroll
        for (int k = 0; k < 4; k++) {
            fa[k] = __ldcs(&src[2 * (size_t)(i + k * stride)]);
            fb[k] = __ldcs(&src[2 * (size_t)(i + k * stride) + 1]);
        }
        #pragma unroll
        for (int k = 0; k < 4; k++) {
            __half2 a0 = __floats2half2_rn(fa[k].x, fa[k].y);
            __half2 a1 = __floats2half2_rn(fa[k].z, fa[k].w);
            __half2 b0 = __floats2half2_rn(fb[k].x, fb[k].y);
            __half2 b1 = __floats2half2_rn(fb[k].z, fb[k].w);
            uint4 u;
            u.x = *(unsigned*)&a0; u.y = *(unsigned*)&a1;
            u.z = *(unsigned*)&b0; u.w = *(unsigned*)&b1;
            dst[i + k * stride] = u;
        }
    }
    for (; i < nOut; i += stride) {
        float4 fa = __ldcs(&src[2 * (size_t)i]);
        float4 fb = __ldcs(&src[2 * (size_t)i + 1]);
        __half2 a0 = __floats2half2_rn(fa.x, fa.y);
        __half2 a1 = __floats2half2_rn(fa.z, fa.w);
        __half2 b0 = __floats2half2_rn(fb.x, fb.y);
        __half2 b1 = __floats2half2_rn(fb.z, fb.w);
        uint4 u;
        u.x = *(unsigned*)&a0; u.y = *(unsigned*)&a1;
        u.z = *(unsigned*)&b0; u.w = *(unsigned*)&b1;
        dst[i] = u;
    }
}

// ---- pass 2: gather + pool -----------------------------------------------------
// 128 threads per CTA, one batch row. Split-pool: threads 0-63 do TITLE,
// threads 64-127 do DESC. Each thread owns 8 dims (one LDG.128 per token),
// hmax2 for max (exact), fp32 sums. No cross-thread merging at all.
__global__ __launch_bounds__(128, 8)
void swem_cat_kernel(const void* __restrict__ title_v,
                     const void* __restrict__ desc_v,
                     const void* __restrict__ tlen_v,
                     const void* __restrict__ dlen_v,
                     float* __restrict__ out)
{
    __shared__ int s_off[TT + TD];   // pre-scaled byte offsets (idx * 1024)
    __shared__ int s_len[2];
    __shared__ int s_is64;

    const int b   = blockIdx.x;
    const int tid = threadIdx.x;
    const int grp = tid >> 6;        // 0 = title, 1 = desc
    const int l64 = tid & 63;

    // dtype detection: int64 vs int32 indices (values < 34836 => high word 0)
    if (tid < 32) {
        unsigned hi  = ((const unsigned*)title_v)[2 * tid + 1];
        unsigned any = __ballot_sync(0xffffffffu, hi != 0u);
        if (tid == 0) s_is64 = (any == 0u) ? 1 : 0;
    }
    __syncthreads();

    if (s_is64) {
        const long long* tp = (const long long*)title_v + (long long)b * TT;
        const long long* dp = (const long long*)desc_v  + (long long)b * TD;
        if (tid < TT) s_off[tid] = ((int)tp[tid]) << 10;
        for (int i = tid; i < TD; i += 128) s_off[TT + i] = ((int)dp[i]) << 10;
        if (tid == 0) {
            s_len[0] = (int)((const long long*)tlen_v)[b];
            s_len[1] = (int)((const long long*)dlen_v)[b];
        }
    } else {
        const int* tp = (const int*)title_v + b * TT;
        const int* dp = (const int*)desc_v  + b * TD;
        if (tid < TT) s_off[tid] = tp[tid] << 10;
        for (int i = tid; i < TD; i += 128) s_off[TT + i] = dp[i] << 10;
        if (tid == 0) {
            s_len[0] = ((const int*)tlen_v)[b];
            s_len[1] = ((const int*)dlen_v)[b];
        }
    }
    __syncthreads();

    const char* hbase = (const char*)g_w2v_h + l64 * 16;   // this thread's 8-dim slice
    float* orow = out + (size_t)b * (4 * DIM) + l64 * 8;

    const __half2 NEGH2 = __halves2half2(__ushort_as_half(0xFC00),
                                         __ushort_as_half(0xFC00)); // (-inf,-inf)

    __half2 mx0 = NEGH2, mx1 = NEGH2, mx2 = NEGH2, mx3 = NEGH2;
    float sm0=0.f, sm1=0.f, sm2=0.f, sm3=0.f, sm4=0.f, sm5=0.f, sm6=0.f, sm7=0.f;

    if (grp == 0) {
        // ------------------------- TITLE (threads 0-63) ----------------------
        const int tl = s_len[0];
        #pragma unroll 4
        for (int t = 0; t < tl; t++) {
            const uint4 u = *(const uint4*)(hbase + s_off[t]);
            const __half2 h0 = *(const __half2*)&u.x, h1 = *(const __half2*)&u.y;
            const __half2 h2 = *(const __half2*)&u.z, h3 = *(const __half2*)&u.w;
            mx0 = __hmax2(mx0, h0); mx1 = __hmax2(mx1, h1);
            mx2 = __hmax2(mx2, h2); mx3 = __hmax2(mx3, h3);
            float2 f;
            f = __half22float2(h0); sm0 += f.x; sm1 += f.y;
            f = __half22float2(h1); sm2 += f.x; sm3 += f.y;
            f = __half22float2(h2); sm4 += f.x; sm5 += f.y;
            f = __half22float2(h3); sm6 += f.x; sm7 += f.y;
        }
        float4 mxa, mxb, ava, avb;
        if (tl > 0) {
            float2 m0 = __half22float2(mx0), m1 = __half22float2(mx1);
            float2 m2 = __half22float2(mx2), m3 = __half22float2(mx3);
            mxa = make_float4(m0.x, m0.y, m1.x, m1.y);
            mxb = make_float4(m2.x, m2.y, m3.x, m3.y);
            const float inv = 1.0f / (float)tl;
            ava = make_float4(sm0 * inv, sm1 * inv, sm2 * inv, sm3 * inv);
            avb = make_float4(sm4 * inv, sm5 * inv, sm6 * inv, sm7 * inv);
        } else {
            mxa = mxb = ava = avb = make_float4(0.f, 0.f, 0.f, 0.f);
        }
        *(float4*)(orow)               = mxa;   // t_max -> [0,512)
        *(float4*)(orow + 4)           = mxb;
        *(float4*)(orow + 2 * DIM)     = ava;   // t_avg -> [1024,1536)
        *(float4*)(orow + 2 * DIM + 4) = avb;
    } else {
        // ------------------------- DESC (threads 64-127) ---------------------
        const int dl = s_len[1];
        #pragma unroll 8
        for (int t = 0; t < dl; t++) {
            const uint4 u = *(const uint4*)(hbase + s_off[TT + t]);
            const __half2 h0 = *(const __half2*)&u.x, h1 = *(const __half2*)&u.y;
            const __half2 h2 = *(const __half2*)&u.z, h3 = *(const __half2*)&u.w;
            mx0 = __hmax2(mx0, h0); mx1 = __hmax2(mx1, h1);
            mx2 = __hmax2(mx2, h2); mx3 = __hmax2(mx3, h3);
            float2 f;
            f = __half22float2(h0); sm0 += f.x; sm1 += f.y;
            f = __half22float2(h1); sm2 += f.x; sm3 += f.y;
            f = __half22float2(h2); sm4 += f.x; sm5 += f.y;
            f = __half22float2(h3); sm6 += f.x; sm7 += f.y;
        }
        float4 mxa, mxb, ava, avb;
        if (dl > 0) {
            float2 m0 = __half22float2(mx0), m1 = __half22float2(mx1);
            float2 m2 = __half22float2(mx2), m3 = __half22float2(mx3);
            mxa = make_float4(m0.x, m0.y, m1.x, m1.y);
            mxb = make_float4(m2.x, m2.y, m3.x, m3.y);
            const float inv = 1.0f / (float)dl;
            ava = make_float4(sm0 * inv, sm1 * inv, sm2 * inv, sm3 * inv);
            avb = make_float4(sm4 * inv, sm5 * inv, sm6 * inv, sm7 * inv);
        } else {
            mxa = mxb = ava = avb = make_float4(0.f, 0.f, 0.f, 0.f);
        }
        *(float4*)(orow + DIM)         = mxa;   // d_max -> [512,1024)
        *(float4*)(orow + DIM + 4)     = mxb;
        *(float4*)(orow + 3 * DIM)     = ava;   // d_avg -> [1536,2048)
        *(float4*)(orow + 3 * DIM + 4) = avb;
    }
}

extern "C" void kernel_launch(void* const* d_in, const int* in_sizes, int n_in,
                              void* d_out, int out_size)
{
    const void* title = d_in[0];
    const void* desc  = d_in[1];
    const void* tlen  = d_in[2];
    const void* dlen  = d_in[3];
    const float* w2v  = (const float*)d_in[n_in - 1];
    float* out        = (float*)d_out;

    const int B = in_sizes[2];                        // t_len has B elements

    long long w2v_elems = in_sizes[n_in - 1];
    long long rows = w2v_elems / DIM;
    if (rows > MAX_ROWS) rows = MAX_ROWS;
    const int nOut = (int)(rows * (DIM / 8));         // uint4 (8 halves) chunks

    __half* dsth;
    cudaGetSymbolAddress((void**)&dsth, g_w2v_h);     // address only, no alloc

    w2v_convert_kernel<<<592, 256>>>((const float4*)w2v, (uint4*)dsth, nOut);
    swem_cat_kernel<<<B, 128>>>(title, desc, tlen, dlen, out);
}